// round 12
// baseline (speedup 1.0000x reference)
#include <cuda_runtime.h>
#include <cstdint>

// Problem constants
constexpr int B_   = 8;
constexpr int H_   = 8;
constexpr int LQ_  = 1024;
constexpr int LM_  = 4096;
constexpr int DM_  = 512;
constexpr int DK_  = 64;
constexpr int TOPK_ = 32;

// Attention kernel tiling
constexpr int QT   = 32;    // queries per block (4 rows per warp)
constexpr int CK   = 128;   // key chunk cached in smem (32 KB)

// Scratch (static device arrays: allocation-free)
__device__ float g_q[B_*H_*LQ_*DK_];   // 16 MB  [B,H,LQ,Dk]
__device__ float g_k[B_*H_*LM_*DK_];   // 64 MB  [B,H,LM,Dk]
__device__ float g_v[B_*H_*LM_*DK_];   // 64 MB  [B,H,LM,Dk]
__device__ float g_x[B_*LQ_*DM_];      // 16 MB  [B,LQ,DM] pre-output-proj

// ---------------- attention smem layout (floats) ---------------------------
constexpr int OFF_QS  = 0;                 // 2048 : Q tile 32x64
constexpr int OFF_KS  = OFF_QS + QT*DK_;   // 8192 : K chunk 128x64, xor-swizzled float4
constexpr int OFF_SCC = OFF_KS + CK*DK_;   // 4096 : score staging 32x128 (ordu uints)
constexpr int SMEM_FLOATS = OFF_SCC + QT*CK;
constexpr int SMEM_BYTES  = SMEM_FLOATS * 4;   // 57344 B

// order-preserving float -> uint, and inverse
__device__ __forceinline__ unsigned ordu(float x) {
    unsigned u = __float_as_uint(x);
    return (u & 0x80000000u) ? ~u : (u | 0x80000000u);
}
__device__ __forceinline__ float iordu(unsigned v) {
    unsigned u = (v & 0x80000000u) ? (v ^ 0x80000000u) : ~v;
    return __uint_as_float(u);
}

// ---------------- packed f32x2 primitives (lanewise IEEE fp32) -------------
typedef unsigned long long ull;

__device__ __forceinline__ ull pack2(float lo, float hi) {
    ull d; asm("mov.b64 %0, {%1, %2};" : "=l"(d) : "f"(lo), "f"(hi)); return d;
}
__device__ __forceinline__ void unpack2(ull v, float& lo, float& hi) {
    asm("mov.b64 {%0, %1}, %2;" : "=f"(lo), "=f"(hi) : "l"(v));
}
__device__ __forceinline__ ull fma2(ull a, ull b, ull c) {
    ull d; asm("fma.rn.f32x2 %0, %1, %2, %3;" : "=l"(d) : "l"(a), "l"(b), "l"(c)); return d;
}
__device__ __forceinline__ ull mul2(ull a, ull b) {
    ull d; asm("mul.rn.f32x2 %0, %1, %2;" : "=l"(d) : "l"(a), "l"(b)); return d;
}
__device__ __forceinline__ ull add2(ull a, ull b) {
    ull d; asm("add.rn.f32x2 %0, %1, %2;" : "=l"(d) : "l"(a), "l"(b)); return d;
}

// B smem row layout: per-tx pad to 10 floats -> 16 distinct banks for the
// 16 tx groups (10*tx mod 32 all distinct), 8B-aligned pairs for LDS.64.
constexpr int BROW = 160;   // 16 tx-groups * 10 floats
__device__ __forceinline__ int bswz(int n) { return (n >> 3) * 10 + (n & 7); }

// ---------------------------------------------------------------------------
// Shared SGEMM body (VERBATIM round-8 best): C = A[M,512] @ W[512,512]^T + bias.
// f32x2 packed FMA inner loop; per-element arithmetic (values and order)
// IDENTICAL to the scalar two-level version of rounds 2-7.
// 256 threads, 8x8 per thread, 128x128 tile at (m0, n0).
// ---------------------------------------------------------------------------
__device__ __forceinline__ void gemm_body(
    const float* __restrict__ A, const float* __restrict__ W,
    const float* __restrict__ bias, float* __restrict__ C,
    int L, int head_major, int m0, int n0)
{
    __shared__ __align__(16) float AsD[2][8][256];   // duplicated A: 16 KB
    __shared__ __align__(16) float Bs [2][8][BROW];  // padded B: 10 KB

    const int t  = threadIdx.x;
    const int tx = t & 15;
    const int ty = t >> 4;
    const int lr = t >> 1;
    const int lc = (t & 1) << 2;

    const float* Ap = A + (size_t)(m0 + lr) * DM_ + lc;
    const float* Wp = W + (size_t)(n0 + lr) * DM_ + lc;
    const int bofs = bswz(lr);

    // prologue: stage k-tile 0 into buffer 0
    {
        float4 av = *(const float4*)(Ap);
        float4 wv = *(const float4*)(Wp);
        ((ull*)AsD[0][lc+0])[lr] = pack2(av.x, av.x);
        ((ull*)AsD[0][lc+1])[lr] = pack2(av.y, av.y);
        ((ull*)AsD[0][lc+2])[lr] = pack2(av.z, av.z);
        ((ull*)AsD[0][lc+3])[lr] = pack2(av.w, av.w);
        Bs[0][lc+0][bofs] = wv.x;
        Bs[0][lc+1][bofs] = wv.y;
        Bs[0][lc+2][bofs] = wv.z;
        Bs[0][lc+3][bofs] = wv.w;
    }
    __syncthreads();

    ull acc2[8][4];
    #pragma unroll
    for (int i = 0; i < 8; i++)
        #pragma unroll
        for (int j = 0; j < 4; j++) acc2[i][j] = pack2(0.f, 0.f);

    #pragma unroll 1
    for (int k0 = 0; k0 < DM_; k0 += 8) {
        const int  p    = (k0 >> 3) & 1;
        const bool more = (k0 + 8) < DM_;
        float4 av, wv;
        if (more) {
            av = *(const float4*)(Ap + k0 + 8);
            wv = *(const float4*)(Wp + k0 + 8);
        }

        ull cacc2[8][4];
        #pragma unroll
        for (int k = 0; k < 8; k++) {
            // a (duplicated) : 8 ull = 4x LDS.128 broadcast
            ull a2[8];
            {
                const ulonglong2* ar = (const ulonglong2*)&AsD[p][k][0];
                #pragma unroll
                for (int ii = 0; ii < 4; ii++) {
                    ulonglong2 v = ar[ty*4 + ii];
                    a2[2*ii]   = v.x;
                    a2[2*ii+1] = v.y;
                }
            }
            // b pairs: 4x LDS.64, conflict-free via 10-float padding
            ull b2[4];
            {
                const ull* br = (const ull*)&Bs[p][k][tx*10];
                #pragma unroll
                for (int j = 0; j < 4; j++) b2[j] = br[j];
            }
            if (k == 0) {
                #pragma unroll
                for (int i = 0; i < 8; i++)
                    #pragma unroll
                    for (int j = 0; j < 4; j++)
                        cacc2[i][j] = mul2(a2[i], b2[j]);
            } else {
                #pragma unroll
                for (int i = 0; i < 8; i++)
                    #pragma unroll
                    for (int j = 0; j < 4; j++)
                        cacc2[i][j] = fma2(a2[i], b2[j], cacc2[i][j]);
            }
        }
        #pragma unroll
        for (int i = 0; i < 8; i++)
            #pragma unroll
            for (int j = 0; j < 4; j++)
                acc2[i][j] = add2(acc2[i][j], cacc2[i][j]);

        if (more) {
            const int q = p ^ 1;
            ((ull*)AsD[q][lc+0])[lr] = pack2(av.x, av.x);
            ((ull*)AsD[q][lc+1])[lr] = pack2(av.y, av.y);
            ((ull*)AsD[q][lc+2])[lr] = pack2(av.z, av.z);
            ((ull*)AsD[q][lc+3])[lr] = pack2(av.w, av.w);
            Bs[q][lc+0][bofs] = wv.x;
            Bs[q][lc+1][bofs] = wv.y;
            Bs[q][lc+2][bofs] = wv.z;
            Bs[q][lc+3][bofs] = wv.w;
        }
        __syncthreads();
    }

    #pragma unroll
    for (int i = 0; i < 8; i++) {
        int m  = m0 + ty*8 + i;
        int bb_ = m / L;
        int l   = m - bb_ * L;
        #pragma unroll
        for (int j = 0; j < 4; j++) {
            float lo, hi;
            unpack2(acc2[i][j], lo, hi);
            int n0j = n0 + tx*8 + 2*j;
            float v0 = lo + bias[n0j];
            float v1 = hi + bias[n0j + 1];
            if (head_major) {
                int hh0 = n0j >> 6, dk0 = n0j & 63;
                int hh1 = (n0j+1) >> 6, dk1 = (n0j+1) & 63;
                C[((size_t)(bb_*H_ + hh0) * L + l) * DK_ + dk0] = v0;
                C[((size_t)(bb_*H_ + hh1) * L + l) * DK_ + dk1] = v1;
            } else {
                C[(size_t)m * DM_ + n0j]     = v0;
                C[(size_t)m * DM_ + n0j + 1] = v1;
            }
        }
    }
}

// Merged Q/K/V projection: grid (64 + 256 + 256, 4).
__global__ void __launch_bounds__(256, 1)
qkv_gemm_kernel(const float* __restrict__ q_in, const float* __restrict__ k_in,
                const float* __restrict__ v_in,
                const float* __restrict__ Wq, const float* __restrict__ bq,
                const float* __restrict__ Wk, const float* __restrict__ bk,
                const float* __restrict__ Wv, const float* __restrict__ bv,
                float* __restrict__ pq, float* __restrict__ pk, float* __restrict__ pv)
{
    const int bx = blockIdx.x;
    const float *A, *W, *bias; float* C; int L, mblk;
    if (bx < 64)        { A = q_in; W = Wq; bias = bq; C = pq; L = LQ_; mblk = bx; }
    else if (bx < 320)  { A = k_in; W = Wk; bias = bk; C = pk; L = LM_; mblk = bx - 64; }
    else                { A = v_in; W = Wv; bias = bv; C = pv; L = LM_; mblk = bx - 320; }
    gemm_body(A, W, bias, C, L, 1, mblk * 128, blockIdx.y * 128);
}

// Output projection: plain row-major.
__global__ void __launch_bounds__(256, 1)
out_gemm_kernel(const float* __restrict__ A, const float* __restrict__ W,
                const float* __restrict__ bias, float* __restrict__ C)
{
    gemm_body(A, W, bias, C, LQ_, 0, blockIdx.x * 128, blockIdx.y * 128);
}

// ---------------------------------------------------------------------------
// Fused scores + EXACT top-32 + softmax + V gather — round-11 pipelined
// structure and bit-identical arithmetic/selection order. TWO changes:
//   1. __launch_bounds__(256, 2): 128-reg budget so ptxas can pre-stage LDS
//      loads across iterations (round 7-11 ran at 64-80 regs and stalled
//      the fma pipe at ~50% of its rt ceiling).
//   2. K loads manually double-buffered one d4 iteration ahead (loads
//      reordered only — the per-(q,k) FMA expression is untouched, so
//      scores and selection are bit-identical).
// ---------------------------------------------------------------------------
__global__ void __launch_bounds__(256, 2)
attn_topk_kernel(const float* __restrict__ gq, const float* __restrict__ gk,
                 const float* __restrict__ gv, float* __restrict__ gx)
{
    extern __shared__ float sm[];
    float*    qs  = sm + OFF_QS;
    float*    ks  = sm + OFF_KS;                 // xor-swizzled float4 tile
    unsigned* scC = (unsigned*)(sm + OFF_SCC);   // QT x CK ordu scores

    const int t    = threadIdx.x;
    const int lane = t & 31;
    const int w    = t >> 5;               // warp id; owns rows 4w..4w+3
    const int qt0  = blockIdx.x * QT;
    const int h    = blockIdx.y;
    const int b    = blockIdx.z;
    const unsigned FULL = 0xffffffffu;

    // score-phase ownership: keys {kk, kk+64}, queries qh..qh+7
    const int kk = t & 63;
    const int qh = (t >> 6) << 3;

    // ---- load Q tile (32x64 fp32) ----
    const float* qbase = gq + ((size_t)(b*H_ + h) * LQ_ + qt0) * DK_;
    #pragma unroll
    for (int i = t; i < QT*DK_/4; i += 256)
        ((float4*)qs)[i] = ((const float4*)qbase)[i];

    const float* kbase = gk + (size_t)(b*H_ + h) * LM_ * DK_;

    // running top-32 state for the four rows owned by this warp
    unsigned bval[4] = {0u, 0u, 0u, 0u};
    int      bidx[4] = {0, 0, 0, 0};
    unsigned m[4]    = {0u, 0u, 0u, 0u};

    // ---- stage K chunk (CK x 64) with XOR swizzle: conflict-free ----
    auto stage = [&](int c0) {
        #pragma unroll
        for (int i = t; i < CK*16; i += 256) {
            int row = i >> 4, col = i & 15;
            float4 v4 = ((const float4*)(kbase + (size_t)(c0 + row) * DK_))[col];
            ((float4*)ks)[(row << 4) | (col ^ (row & 15))] = v4;
        }
    };

    // ---- scores: thread owns keys kk, kk+64 and queries qh..qh+7;
    //      per-(q,k) FMA statement identical to rounds 4-11; K loads
    //      double-buffered one d4 iteration ahead (reorder only) ----
    auto do_scores = [&]() {
        float acc0[8], acc1[8];
        #pragma unroll
        for (int qi = 0; qi < 8; qi++) { acc0[qi] = 0.f; acc1[qi] = 0.f; }
        const float4* ks4 = (const float4*)ks;
        const int kk2 = kk + 64;

        float4 kv0 = ks4[(kk  << 4) | (0 ^ (kk  & 15))];
        float4 kv1 = ks4[(kk2 << 4) | (0 ^ (kk2 & 15))];
        #pragma unroll
        for (int d4 = 0; d4 < DK_/4; d4++) {
            float4 c0v = kv0, c1v = kv1;
            if (d4 + 1 < DK_/4) {
                kv0 = ks4[(kk  << 4) | ((d4+1) ^ (kk  & 15))];
                kv1 = ks4[(kk2 << 4) | ((d4+1) ^ (kk2 & 15))];
            }
            #pragma unroll
            for (int qi = 0; qi < 8; qi++) {
                float4 qv = ((const float4*)(qs + (qh + qi)*DK_))[d4];
                acc0[qi] += c0v.x*qv.x + c0v.y*qv.y + c0v.z*qv.z + c0v.w*qv.w;
                acc1[qi] += c1v.x*qv.x + c1v.y*qv.y + c1v.z*qv.z + c1v.w*qv.w;
            }
        }
        #pragma unroll
        for (int qi = 0; qi < 8; qi++) {
            scC[(qh + qi)*CK + kk ] = ordu(acc0[qi] * 0.125f);  // 1/sqrt(64)
            scC[(qh + qi)*CK + kk2] = ordu(acc1[qi] * 0.125f);
        }
    };

    // ---- select: warp w updates running top-32 for rows 4w..4w+3 from the
    //      scC scores of the chunk that starts at key index 'base' ----
    auto select_chunk = [&](int base) {
        #pragma unroll 1
        for (int rr = 0; rr < 4; rr++) {
            const int rowi = 4*w + rr;
            const unsigned* srow = scC + rowi*CK;

            bool slow;
            if (base == 0) {
                slow = true;   // includes initial fill
            } else {
                // fast path: one uint4 per lane covers the 128-key chunk.
                // Skipping when nothing exceeds m is exactly equivalent to
                // sequential processing (m is monotone non-decreasing).
                uint4 uu = ((const uint4*)srow)[lane];
                bool any = (uu.x > m[rr]) | (uu.y > m[rr]) |
                           (uu.z > m[rr]) | (uu.w > m[rr]);
                slow = (__ballot_sync(FULL, any) != 0u);
            }

            if (slow) {
                #pragma unroll 1
                for (int bb = 0; bb < CK/32; bb++) {
                    const int i0 = base + bb*32;
                    unsigned u = srow[bb*32 + lane];

                    if (base == 0 && bb == 0) {     // initial fill
                        bval[rr] = u; bidx[rr] = lane;
                        m[rr] = __reduce_min_sync(FULL, bval[rr]);
                        continue;
                    }

                    unsigned hit = __ballot_sync(FULL, u > m[rr]);
                    while (hit) {                    // warp-uniform rare path
                        int s = __ffs(hit) - 1; hit &= hit - 1;
                        unsigned uc = __shfl_sync(FULL, u, s);
                        if (uc > m[rr]) {            // recheck vs updated m
                            int ic = i0 + s;
                            unsigned em = __ballot_sync(FULL, bval[rr] == m[rr]);
                            int el;
                            if (__popc(em) > 1) {
                                // tie on min: evict LARGER index (jax keeps lower)
                                int cb = ((em >> lane) & 1) ? bidx[rr] : -1;
                                int mx = __reduce_max_sync(FULL, cb);
                                el = __ffs(__ballot_sync(FULL,
                                        (bval[rr] == m[rr]) && (bidx[rr] == mx))) - 1;
                            } else {
                                el = __ffs(em) - 1;
                            }
                            if (lane == el) { bval[rr] = uc; bidx[rr] = ic; }
                            m[rr] = __reduce_min_sync(FULL, bval[rr]);
                        }
                    }
                }
            }
        }
    };

    // ---- software-pipelined main loop ----
    stage(0);
    __syncthreads();
    do_scores();
    __syncthreads();

    #pragma unroll 1
    for (int c0 = CK; c0 < LM_; c0 += CK) {
        stage(c0);                 // LDG in flight while select runs
        select_chunk(c0 - CK);     // reads scC of previous chunk
        __syncthreads();
        do_scores();               // overwrites scC (guarded by sync)
        __syncthreads();
    }
    select_chunk(LM_ - CK);

    // ---- softmax + weighted V gather for the four rows ----
    const float* vbase = gv + (size_t)(b*H_ + h) * LM_ * DK_;
    #pragma unroll 1
    for (int rr = 0; rr < 4; rr++) {
        float v  = iordu(bval[rr]);
        float mx = v;
        #pragma unroll
        for (int off = 16; off; off >>= 1)
            mx = fmaxf(mx, __shfl_xor_sync(FULL, mx, off));
        float e = __expf(v - mx);
        float s = e;
        #pragma unroll
        for (int off = 16; off; off >>= 1)
            s += __shfl_xor_sync(FULL, s, off);
        float wgt = e / s;

        float a0 = 0.f, a1 = 0.f;
        #pragma unroll 4
        for (int it = 0; it < TOPK_; it++) {
            float wi = __shfl_sync(FULL, wgt, it);
            int   ki = __shfl_sync(FULL, bidx[rr], it);
            const float* vr = vbase + (size_t)ki * DK_;
            a0 = fmaf(wi, vr[lane],      a0);
            a1 = fmaf(wi, vr[lane + 32], a1);
        }
        float* orow = gx + ((size_t)b * LQ_ + (qt0 + 4*w + rr)) * DM_ + h*DK_;
        orow[lane]      = a0;
        orow[lane + 32] = a1;
    }
}

// ---------------------------------------------------------------------------
extern "C" void kernel_launch(void* const* d_in, const int* in_sizes, int n_in,
                              void* d_out, int out_size)
{
    const float* query = (const float*)d_in[0];
    const float* key   = (const float*)d_in[1];
    const float* value = (const float*)d_in[2];
    const float* Wq    = (const float*)d_in[3];
    const float* bq    = (const float*)d_in[4];
    const float* Wk    = (const float*)d_in[5];
    const float* bk    = (const float*)d_in[6];
    const float* Wv    = (const float*)d_in[7];
    const float* bv    = (const float*)d_in[8];
    const float* Wo    = (const float*)d_in[9];
    const float* bo    = (const float*)d_in[10];
    float* out = (float*)d_out;

    float *pq, *pk, *pv, *px;
    cudaGetSymbolAddress((void**)&pq, g_q);
    cudaGetSymbolAddress((void**)&pk, g_k);
    cudaGetSymbolAddress((void**)&pv, g_v);
    cudaGetSymbolAddress((void**)&px, g_x);

    cudaFuncSetAttribute(attn_topk_kernel,
                         cudaFuncAttributeMaxDynamicSharedMemorySize, SMEM_BYTES);

    // merged Q/K/V projections into head-major scratch (round-8 geometry)
    qkv_gemm_kernel<<<dim3(576, DM_/128), 256>>>(query, key, value,
                                                 Wq, bq, Wk, bk, Wv, bv,
                                                 pq, pk, pv);

    // fused scores + topk + softmax + gather
    attn_topk_kernel<<<dim3(LQ_/QT, H_, B_), 256, SMEM_BYTES>>>(pq, pk, pv, px);

    // output projection (plain row-major)
    out_gemm_kernel<<<dim3(B_*LQ_/128, DM_/128), 256>>>(px, Wo, bo, out);
}

// round 13
// speedup vs baseline: 1.0714x; 1.0714x over previous
#include <cuda_runtime.h>
#include <cstdint>

// Problem constants
constexpr int B_   = 8;
constexpr int H_   = 8;
constexpr int LQ_  = 1024;
constexpr int LM_  = 4096;
constexpr int DM_  = 512;
constexpr int DK_  = 64;
constexpr int TOPK_ = 32;

// Attention kernel tiling
constexpr int QT   = 32;    // queries per block (4 rows per warp)
constexpr int CK   = 128;   // key chunk cached in smem (32 KB)

// Scratch (static device arrays: allocation-free)
__device__ float g_q[B_*H_*LQ_*DK_];   // 16 MB  [B,H,LQ,Dk]
__device__ float g_k[B_*H_*LM_*DK_];   // 64 MB  [B,H,LM,Dk]
__device__ float g_v[B_*H_*LM_*DK_];   // 64 MB  [B,H,LM,Dk]
__device__ float g_x[B_*LQ_*DM_];      // 16 MB  [B,LQ,DM] pre-output-proj

// ---------------- attention smem layout (floats) ---------------------------
constexpr int OFF_QS  = 0;                 // 2048 : Q tile 32x64
constexpr int OFF_KS  = OFF_QS + QT*DK_;   // 8192 : K chunk 128x64, xor-swizzled float4
constexpr int SMEM_FLOATS = OFF_KS + CK*DK_;
constexpr int SMEM_BYTES  = SMEM_FLOATS * 4;   // 40960 B (no score staging!)

// order-preserving float -> uint, and inverse
__device__ __forceinline__ unsigned ordu(float x) {
    unsigned u = __float_as_uint(x);
    return (u & 0x80000000u) ? ~u : (u | 0x80000000u);
}
__device__ __forceinline__ float iordu(unsigned v) {
    unsigned u = (v & 0x80000000u) ? (v ^ 0x80000000u) : ~v;
    return __uint_as_float(u);
}

// ---------------- packed f32x2 primitives (lanewise IEEE fp32) -------------
typedef unsigned long long ull;

__device__ __forceinline__ ull pack2(float lo, float hi) {
    ull d; asm("mov.b64 %0, {%1, %2};" : "=l"(d) : "f"(lo), "f"(hi)); return d;
}
__device__ __forceinline__ void unpack2(ull v, float& lo, float& hi) {
    asm("mov.b64 {%0, %1}, %2;" : "=f"(lo), "=f"(hi) : "l"(v));
}
__device__ __forceinline__ ull fma2(ull a, ull b, ull c) {
    ull d; asm("fma.rn.f32x2 %0, %1, %2, %3;" : "=l"(d) : "l"(a), "l"(b), "l"(c)); return d;
}
__device__ __forceinline__ ull mul2(ull a, ull b) {
    ull d; asm("mul.rn.f32x2 %0, %1, %2;" : "=l"(d) : "l"(a), "l"(b)); return d;
}
__device__ __forceinline__ ull add2(ull a, ull b) {
    ull d; asm("add.rn.f32x2 %0, %1, %2;" : "=l"(d) : "l"(a), "l"(b)); return d;
}

// B smem row layout: per-tx pad to 10 floats -> 16 distinct banks for the
// 16 tx groups (10*tx mod 32 all distinct), 8B-aligned pairs for LDS.64.
constexpr int BROW = 160;   // 16 tx-groups * 10 floats
__device__ __forceinline__ int bswz(int n) { return (n >> 3) * 10 + (n & 7); }

// ---------------------------------------------------------------------------
// Shared SGEMM body (VERBATIM round-8 best): C = A[M,512] @ W[512,512]^T + bias.
// f32x2 packed FMA inner loop; per-element arithmetic (values and order)
// IDENTICAL to the scalar two-level version of rounds 2-7.
// 256 threads, 8x8 per thread, 128x128 tile at (m0, n0).
// ---------------------------------------------------------------------------
__device__ __forceinline__ void gemm_body(
    const float* __restrict__ A, const float* __restrict__ W,
    const float* __restrict__ bias, float* __restrict__ C,
    int L, int head_major, int m0, int n0)
{
    __shared__ __align__(16) float AsD[2][8][256];   // duplicated A: 16 KB
    __shared__ __align__(16) float Bs [2][8][BROW];  // padded B: 10 KB

    const int t  = threadIdx.x;
    const int tx = t & 15;
    const int ty = t >> 4;
    const int lr = t >> 1;
    const int lc = (t & 1) << 2;

    const float* Ap = A + (size_t)(m0 + lr) * DM_ + lc;
    const float* Wp = W + (size_t)(n0 + lr) * DM_ + lc;
    const int bofs = bswz(lr);

    // prologue: stage k-tile 0 into buffer 0
    {
        float4 av = *(const float4*)(Ap);
        float4 wv = *(const float4*)(Wp);
        ((ull*)AsD[0][lc+0])[lr] = pack2(av.x, av.x);
        ((ull*)AsD[0][lc+1])[lr] = pack2(av.y, av.y);
        ((ull*)AsD[0][lc+2])[lr] = pack2(av.z, av.z);
        ((ull*)AsD[0][lc+3])[lr] = pack2(av.w, av.w);
        Bs[0][lc+0][bofs] = wv.x;
        Bs[0][lc+1][bofs] = wv.y;
        Bs[0][lc+2][bofs] = wv.z;
        Bs[0][lc+3][bofs] = wv.w;
    }
    __syncthreads();

    ull acc2[8][4];
    #pragma unroll
    for (int i = 0; i < 8; i++)
        #pragma unroll
        for (int j = 0; j < 4; j++) acc2[i][j] = pack2(0.f, 0.f);

    #pragma unroll 1
    for (int k0 = 0; k0 < DM_; k0 += 8) {
        const int  p    = (k0 >> 3) & 1;
        const bool more = (k0 + 8) < DM_;
        float4 av, wv;
        if (more) {
            av = *(const float4*)(Ap + k0 + 8);
            wv = *(const float4*)(Wp + k0 + 8);
        }

        ull cacc2[8][4];
        #pragma unroll
        for (int k = 0; k < 8; k++) {
            // a (duplicated) : 8 ull = 4x LDS.128 broadcast
            ull a2[8];
            {
                const ulonglong2* ar = (const ulonglong2*)&AsD[p][k][0];
                #pragma unroll
                for (int ii = 0; ii < 4; ii++) {
                    ulonglong2 v = ar[ty*4 + ii];
                    a2[2*ii]   = v.x;
                    a2[2*ii+1] = v.y;
                }
            }
            // b pairs: 4x LDS.64, conflict-free via 10-float padding
            ull b2[4];
            {
                const ull* br = (const ull*)&Bs[p][k][tx*10];
                #pragma unroll
                for (int j = 0; j < 4; j++) b2[j] = br[j];
            }
            if (k == 0) {
                #pragma unroll
                for (int i = 0; i < 8; i++)
                    #pragma unroll
                    for (int j = 0; j < 4; j++)
                        cacc2[i][j] = mul2(a2[i], b2[j]);
            } else {
                #pragma unroll
                for (int i = 0; i < 8; i++)
                    #pragma unroll
                    for (int j = 0; j < 4; j++)
                        cacc2[i][j] = fma2(a2[i], b2[j], cacc2[i][j]);
            }
        }
        #pragma unroll
        for (int i = 0; i < 8; i++)
            #pragma unroll
            for (int j = 0; j < 4; j++)
                acc2[i][j] = add2(acc2[i][j], cacc2[i][j]);

        if (more) {
            const int q = p ^ 1;
            ((ull*)AsD[q][lc+0])[lr] = pack2(av.x, av.x);
            ((ull*)AsD[q][lc+1])[lr] = pack2(av.y, av.y);
            ((ull*)AsD[q][lc+2])[lr] = pack2(av.z, av.z);
            ((ull*)AsD[q][lc+3])[lr] = pack2(av.w, av.w);
            Bs[q][lc+0][bofs] = wv.x;
            Bs[q][lc+1][bofs] = wv.y;
            Bs[q][lc+2][bofs] = wv.z;
            Bs[q][lc+3][bofs] = wv.w;
        }
        __syncthreads();
    }

    #pragma unroll
    for (int i = 0; i < 8; i++) {
        int m  = m0 + ty*8 + i;
        int bb_ = m / L;
        int l   = m - bb_ * L;
        #pragma unroll
        for (int j = 0; j < 4; j++) {
            float lo, hi;
            unpack2(acc2[i][j], lo, hi);
            int n0j = n0 + tx*8 + 2*j;
            float v0 = lo + bias[n0j];
            float v1 = hi + bias[n0j + 1];
            if (head_major) {
                int hh0 = n0j >> 6, dk0 = n0j & 63;
                int hh1 = (n0j+1) >> 6, dk1 = (n0j+1) & 63;
                C[((size_t)(bb_*H_ + hh0) * L + l) * DK_ + dk0] = v0;
                C[((size_t)(bb_*H_ + hh1) * L + l) * DK_ + dk1] = v1;
            } else {
                C[(size_t)m * DM_ + n0j]     = v0;
                C[(size_t)m * DM_ + n0j + 1] = v1;
            }
        }
    }
}

// Merged Q/K/V projection: grid (64 + 256 + 256, 4).
__global__ void __launch_bounds__(256, 1)
qkv_gemm_kernel(const float* __restrict__ q_in, const float* __restrict__ k_in,
                const float* __restrict__ v_in,
                const float* __restrict__ Wq, const float* __restrict__ bq,
                const float* __restrict__ Wk, const float* __restrict__ bk,
                const float* __restrict__ Wv, const float* __restrict__ bv,
                float* __restrict__ pq, float* __restrict__ pk, float* __restrict__ pv)
{
    const int bx = blockIdx.x;
    const float *A, *W, *bias; float* C; int L, mblk;
    if (bx < 64)        { A = q_in; W = Wq; bias = bq; C = pq; L = LQ_; mblk = bx; }
    else if (bx < 320)  { A = k_in; W = Wk; bias = bk; C = pk; L = LM_; mblk = bx - 64; }
    else                { A = v_in; W = Wv; bias = bv; C = pv; L = LM_; mblk = bx - 320; }
    gemm_body(A, W, bias, C, L, 1, mblk * 128, blockIdx.y * 128);
}

// Output projection: plain row-major.
__global__ void __launch_bounds__(256, 1)
out_gemm_kernel(const float* __restrict__ A, const float* __restrict__ W,
                const float* __restrict__ bias, float* __restrict__ C)
{
    gemm_body(A, W, bias, C, LQ_, 0, blockIdx.x * 128, blockIdx.y * 128);
}

// ---------------------------------------------------------------------------
// Fused scores + EXACT top-32 + softmax + V gather — REGISTER-SCORE version:
// warp w computes the scores for ITS OWN rows 4w..4w+3 against all 128 staged
// keys (lane l owns keys {c0 + sub*32 + l}, sub=0..3) and keeps the 16 scores
// in registers; selection runs directly on those registers. The scC smem
// round-trip and its barrier are eliminated (2 syncs/chunk, both for the
// shared K tile only).
// Per-(q,k) FMA statement and per-row batch visit order (i0 = c0 + sub*32,
// sub ascending == old bb order) are IDENTICAL to rounds 4-12
// => scores and selection bit-identical.
// ---------------------------------------------------------------------------
__global__ void __launch_bounds__(256, 3)
attn_topk_kernel(const float* __restrict__ gq, const float* __restrict__ gk,
                 const float* __restrict__ gv, float* __restrict__ gx)
{
    extern __shared__ float sm[];
    float* qs = sm + OFF_QS;
    float* ks = sm + OFF_KS;                 // xor-swizzled float4 tile

    const int t    = threadIdx.x;
    const int lane = t & 31;
    const int w    = t >> 5;               // warp id; owns rows 4w..4w+3
    const int qt0  = blockIdx.x * QT;
    const int h    = blockIdx.y;
    const int b    = blockIdx.z;
    const unsigned FULL = 0xffffffffu;

    // ---- load Q tile (32x64 fp32) ----
    const float* qbase = gq + ((size_t)(b*H_ + h) * LQ_ + qt0) * DK_;
    #pragma unroll
    for (int i = t; i < QT*DK_/4; i += 256)
        ((float4*)qs)[i] = ((const float4*)qbase)[i];

    const float* kbase = gk + (size_t)(b*H_ + h) * LM_ * DK_;

    // running top-32 state for the four rows owned by this warp
    unsigned bval[4] = {0u, 0u, 0u, 0u};
    int      bidx[4] = {0, 0, 0, 0};
    unsigned m[4]    = {0u, 0u, 0u, 0u};

    // this lane's 4 key indices within a chunk (sub*32 + lane) and their
    // swizzle masks (fixed across chunks)
    const int key0 = lane;         // sub 0
    const int key1 = 32 + lane;    // sub 1
    const int key2 = 64 + lane;    // sub 2
    const int key3 = 96 + lane;    // sub 3

    #pragma unroll 1
    for (int c0 = 0; c0 < LM_; c0 += CK) {
        __syncthreads();  // all warps done reading ks of previous chunk

        // ---- stage K chunk (CK x 64) with XOR swizzle: conflict-free ----
        #pragma unroll
        for (int i = t; i < CK*16; i += 256) {
            int row = i >> 4, col = i & 15;
            float4 v4 = ((const float4*)(kbase + (size_t)(c0 + row) * DK_))[col];
            ((float4*)ks)[(row << 4) | (col ^ (row & 15))] = v4;
        }
        __syncthreads();

        // ---- scores in registers: 4 keys (this lane) x 4 rows (this warp);
        //      per-(q,k) FMA statement identical to rounds 4-12 ----
        float acc[4][4];   // [sub][row]
        #pragma unroll
        for (int sub = 0; sub < 4; sub++)
            #pragma unroll
            for (int r = 0; r < 4; r++) acc[sub][r] = 0.f;

        {
            const float4* ks4 = (const float4*)ks;
            const float4* q4  = (const float4*)(qs + (4*w) * DK_);
            #pragma unroll
            for (int d4 = 0; d4 < DK_/4; d4++) {
                float4 kv0 = ks4[(key0 << 4) | (d4 ^ (key0 & 15))];
                float4 kv1 = ks4[(key1 << 4) | (d4 ^ (key1 & 15))];
                float4 kv2 = ks4[(key2 << 4) | (d4 ^ (key2 & 15))];
                float4 kv3 = ks4[(key3 << 4) | (d4 ^ (key3 & 15))];
                #pragma unroll
                for (int r = 0; r < 4; r++) {
                    float4 qv = q4[r*16 + d4];     // broadcast
                    acc[0][r] += kv0.x*qv.x + kv0.y*qv.y + kv0.z*qv.z + kv0.w*qv.w;
                    acc[1][r] += kv1.x*qv.x + kv1.y*qv.y + kv1.z*qv.z + kv1.w*qv.w;
                    acc[2][r] += kv2.x*qv.x + kv2.y*qv.y + kv2.z*qv.z + kv2.w*qv.w;
                    acc[3][r] += kv3.x*qv.x + kv3.y*qv.y + kv3.z*qv.z + kv3.w*qv.w;
                }
            }
        }

        // ---- select on register scores; batch order: sub ascending ----
        #pragma unroll 1
        for (int r = 0; r < 4; r++) {
            unsigned u0 = ordu(acc[0][r] * 0.125f);   // 1/sqrt(64)
            unsigned u1 = ordu(acc[1][r] * 0.125f);
            unsigned u2 = ordu(acc[2][r] * 0.125f);
            unsigned u3 = ordu(acc[3][r] * 0.125f);

            if (c0 != 0) {
                // fast path: skip row if nothing exceeds m[r] (exact: m is
                // monotone non-decreasing, so skipping is equivalent).
                bool any = (u0 > m[r]) | (u1 > m[r]) | (u2 > m[r]) | (u3 > m[r]);
                if (__ballot_sync(FULL, any) == 0u) continue;
            }

            #pragma unroll 1
            for (int sub = 0; sub < 4; sub++) {
                unsigned u = (sub == 0) ? u0 : (sub == 1) ? u1 : (sub == 2) ? u2 : u3;
                const int i0 = c0 + sub*32;

                if (c0 == 0 && sub == 0) {          // initial fill
                    bval[r] = u; bidx[r] = lane;
                    m[r] = __reduce_min_sync(FULL, bval[r]);
                    continue;
                }

                unsigned hit = __ballot_sync(FULL, u > m[r]);
                while (hit) {                        // warp-uniform rare path
                    int s = __ffs(hit) - 1; hit &= hit - 1;
                    unsigned uc = __shfl_sync(FULL, u, s);
                    if (uc > m[r]) {                 // recheck vs updated m
                        int ic = i0 + s;
                        unsigned em = __ballot_sync(FULL, bval[r] == m[r]);
                        int el;
                        if (__popc(em) > 1) {
                            // tie on min: evict LARGER index (jax keeps lower)
                            int cb = ((em >> lane) & 1) ? bidx[r] : -1;
                            int mx = __reduce_max_sync(FULL, cb);
                            el = __ffs(__ballot_sync(FULL,
                                    (bval[r] == m[r]) && (bidx[r] == mx))) - 1;
                        } else {
                            el = __ffs(em) - 1;
                        }
                        if (lane == el) { bval[r] = uc; bidx[r] = ic; }
                        m[r] = __reduce_min_sync(FULL, bval[r]);
                    }
                }
            }
        }
    }

    // ---- softmax + weighted V gather for the four rows ----
    const float* vbase = gv + (size_t)(b*H_ + h) * LM_ * DK_;
    #pragma unroll 1
    for (int rr = 0; rr < 4; rr++) {
        float v  = iordu(bval[rr]);
        float mx = v;
        #pragma unroll
        for (int off = 16; off; off >>= 1)
            mx = fmaxf(mx, __shfl_xor_sync(FULL, mx, off));
        float e = __expf(v - mx);
        float s = e;
        #pragma unroll
        for (int off = 16; off; off >>= 1)
            s += __shfl_xor_sync(FULL, s, off);
        float wgt = e / s;

        float a0 = 0.f, a1 = 0.f;
        #pragma unroll 4
        for (int it = 0; it < TOPK_; it++) {
            float wi = __shfl_sync(FULL, wgt, it);
            int   ki = __shfl_sync(FULL, bidx[rr], it);
            const float* vr = vbase + (size_t)ki * DK_;
            a0 = fmaf(wi, vr[lane],      a0);
            a1 = fmaf(wi, vr[lane + 32], a1);
        }
        float* orow = gx + ((size_t)b * LQ_ + (qt0 + 4*w + rr)) * DM_ + h*DK_;
        orow[lane]      = a0;
        orow[lane + 32] = a1;
    }
}

// ---------------------------------------------------------------------------
extern "C" void kernel_launch(void* const* d_in, const int* in_sizes, int n_in,
                              void* d_out, int out_size)
{
    const float* query = (const float*)d_in[0];
    const float* key   = (const float*)d_in[1];
    const float* value = (const float*)d_in[2];
    const float* Wq    = (const float*)d_in[3];
    const float* bq    = (const float*)d_in[4];
    const float* Wk    = (const float*)d_in[5];
    const float* bk    = (const float*)d_in[6];
    const float* Wv    = (const float*)d_in[7];
    const float* bv    = (const float*)d_in[8];
    const float* Wo    = (const float*)d_in[9];
    const float* bo    = (const float*)d_in[10];
    float* out = (float*)d_out;

    float *pq, *pk, *pv, *px;
    cudaGetSymbolAddress((void**)&pq, g_q);
    cudaGetSymbolAddress((void**)&pk, g_k);
    cudaGetSymbolAddress((void**)&pv, g_v);
    cudaGetSymbolAddress((void**)&px, g_x);

    cudaFuncSetAttribute(attn_topk_kernel,
                         cudaFuncAttributeMaxDynamicSharedMemorySize, SMEM_BYTES);

    // merged Q/K/V projections into head-major scratch (round-8 geometry)
    qkv_gemm_kernel<<<dim3(576, DM_/128), 256>>>(query, key, value,
                                                 Wq, bq, Wk, bk, Wv, bv,
                                                 pq, pk, pv);

    // fused scores + topk + softmax + gather
    attn_topk_kernel<<<dim3(LQ_/QT, H_, B_), 256, SMEM_BYTES>>>(pq, pk, pv, px);

    // output projection (plain row-major)
    out_gemm_kernel<<<dim3(B_*LQ_/128, DM_/128), 256>>>(px, Wo, bo, out);
}

// round 14
// speedup vs baseline: 1.1283x; 1.0531x over previous
#include <cuda_runtime.h>
#include <cstdint>

// Problem constants
constexpr int B_   = 8;
constexpr int H_   = 8;
constexpr int LQ_  = 1024;
constexpr int LM_  = 4096;
constexpr int DM_  = 512;
constexpr int DK_  = 64;
constexpr int TOPK_ = 32;

// Attention kernel tiling
constexpr int QT   = 32;    // queries per block (4 rows per warp)
constexpr int CK   = 128;   // key chunk cached in smem (32 KB)

// Scratch (static device arrays: allocation-free)
__device__ float g_q[B_*H_*LQ_*DK_];   // 16 MB  [B,H,LQ,Dk]
__device__ float g_k[B_*H_*LM_*DK_];   // 64 MB  [B,H,LM,Dk]
__device__ float g_v[B_*H_*LM_*DK_];   // 64 MB  [B,H,LM,Dk]
__device__ float g_x[B_*LQ_*DM_];      // 16 MB  [B,LQ,DM] pre-output-proj

// ---------------- attention smem layout (float units) ----------------------
// qp: 16 row-pairs x 64 dims, f32x2 packed (1024 ull = 8 KB)
// ks: K chunk 128x64, xor-swizzled float4 (32 KB)
constexpr int OFF_QP  = 0;                  // 2048 floats (1024 ull)
constexpr int OFF_KS  = OFF_QP + 2048;      // 8192 floats
constexpr int SMEM_FLOATS = OFF_KS + CK*DK_;
constexpr int SMEM_BYTES  = SMEM_FLOATS * 4;   // 40960 B -> 3 blocks/SM

// order-preserving float -> uint, and inverse
__device__ __forceinline__ unsigned ordu(float x) {
    unsigned u = __float_as_uint(x);
    return (u & 0x80000000u) ? ~u : (u | 0x80000000u);
}
__device__ __forceinline__ float iordu(unsigned v) {
    unsigned u = (v & 0x80000000u) ? (v ^ 0x80000000u) : ~v;
    return __uint_as_float(u);
}

// ---------------- packed f32x2 primitives (lanewise IEEE fp32) -------------
typedef unsigned long long ull;

__device__ __forceinline__ ull pack2(float lo, float hi) {
    ull d; asm("mov.b64 %0, {%1, %2};" : "=l"(d) : "f"(lo), "f"(hi)); return d;
}
__device__ __forceinline__ void unpack2(ull v, float& lo, float& hi) {
    asm("mov.b64 {%0, %1}, %2;" : "=f"(lo), "=f"(hi) : "l"(v));
}
__device__ __forceinline__ ull fma2(ull a, ull b, ull c) {
    ull d; asm("fma.rn.f32x2 %0, %1, %2, %3;" : "=l"(d) : "l"(a), "l"(b), "l"(c)); return d;
}
__device__ __forceinline__ ull mul2(ull a, ull b) {
    ull d; asm("mul.rn.f32x2 %0, %1, %2;" : "=l"(d) : "l"(a), "l"(b)); return d;
}
__device__ __forceinline__ ull add2(ull a, ull b) {
    ull d; asm("add.rn.f32x2 %0, %1, %2;" : "=l"(d) : "l"(a), "l"(b)); return d;
}

// B smem row layout: per-tx pad to 10 floats -> 16 distinct banks for the
// 16 tx groups (10*tx mod 32 all distinct), 8B-aligned pairs for LDS.64.
constexpr int BROW = 160;   // 16 tx-groups * 10 floats
__device__ __forceinline__ int bswz(int n) { return (n >> 3) * 10 + (n & 7); }

// ---------------------------------------------------------------------------
// Shared SGEMM body (VERBATIM round-8 best): C = A[M,512] @ W[512,512]^T + bias.
// f32x2 packed FMA inner loop; per-element arithmetic (values and order)
// IDENTICAL to the scalar two-level version of rounds 2-7.
// 256 threads, 8x8 per thread, 128x128 tile at (m0, n0).
// ---------------------------------------------------------------------------
__device__ __forceinline__ void gemm_body(
    const float* __restrict__ A, const float* __restrict__ W,
    const float* __restrict__ bias, float* __restrict__ C,
    int L, int head_major, int m0, int n0)
{
    __shared__ __align__(16) float AsD[2][8][256];   // duplicated A: 16 KB
    __shared__ __align__(16) float Bs [2][8][BROW];  // padded B: 10 KB

    const int t  = threadIdx.x;
    const int tx = t & 15;
    const int ty = t >> 4;
    const int lr = t >> 1;
    const int lc = (t & 1) << 2;

    const float* Ap = A + (size_t)(m0 + lr) * DM_ + lc;
    const float* Wp = W + (size_t)(n0 + lr) * DM_ + lc;
    const int bofs = bswz(lr);

    // prologue: stage k-tile 0 into buffer 0
    {
        float4 av = *(const float4*)(Ap);
        float4 wv = *(const float4*)(Wp);
        ((ull*)AsD[0][lc+0])[lr] = pack2(av.x, av.x);
        ((ull*)AsD[0][lc+1])[lr] = pack2(av.y, av.y);
        ((ull*)AsD[0][lc+2])[lr] = pack2(av.z, av.z);
        ((ull*)AsD[0][lc+3])[lr] = pack2(av.w, av.w);
        Bs[0][lc+0][bofs] = wv.x;
        Bs[0][lc+1][bofs] = wv.y;
        Bs[0][lc+2][bofs] = wv.z;
        Bs[0][lc+3][bofs] = wv.w;
    }
    __syncthreads();

    ull acc2[8][4];
    #pragma unroll
    for (int i = 0; i < 8; i++)
        #pragma unroll
        for (int j = 0; j < 4; j++) acc2[i][j] = pack2(0.f, 0.f);

    #pragma unroll 1
    for (int k0 = 0; k0 < DM_; k0 += 8) {
        const int  p    = (k0 >> 3) & 1;
        const bool more = (k0 + 8) < DM_;
        float4 av, wv;
        if (more) {
            av = *(const float4*)(Ap + k0 + 8);
            wv = *(const float4*)(Wp + k0 + 8);
        }

        ull cacc2[8][4];
        #pragma unroll
        for (int k = 0; k < 8; k++) {
            // a (duplicated) : 8 ull = 4x LDS.128 broadcast
            ull a2[8];
            {
                const ulonglong2* ar = (const ulonglong2*)&AsD[p][k][0];
                #pragma unroll
                for (int ii = 0; ii < 4; ii++) {
                    ulonglong2 v = ar[ty*4 + ii];
                    a2[2*ii]   = v.x;
                    a2[2*ii+1] = v.y;
                }
            }
            // b pairs: 4x LDS.64, conflict-free via 10-float padding
            ull b2[4];
            {
                const ull* br = (const ull*)&Bs[p][k][tx*10];
                #pragma unroll
                for (int j = 0; j < 4; j++) b2[j] = br[j];
            }
            if (k == 0) {
                #pragma unroll
                for (int i = 0; i < 8; i++)
                    #pragma unroll
                    for (int j = 0; j < 4; j++)
                        cacc2[i][j] = mul2(a2[i], b2[j]);
            } else {
                #pragma unroll
                for (int i = 0; i < 8; i++)
                    #pragma unroll
                    for (int j = 0; j < 4; j++)
                        cacc2[i][j] = fma2(a2[i], b2[j], cacc2[i][j]);
            }
        }
        #pragma unroll
        for (int i = 0; i < 8; i++)
            #pragma unroll
            for (int j = 0; j < 4; j++)
                acc2[i][j] = add2(acc2[i][j], cacc2[i][j]);

        if (more) {
            const int q = p ^ 1;
            ((ull*)AsD[q][lc+0])[lr] = pack2(av.x, av.x);
            ((ull*)AsD[q][lc+1])[lr] = pack2(av.y, av.y);
            ((ull*)AsD[q][lc+2])[lr] = pack2(av.z, av.z);
            ((ull*)AsD[q][lc+3])[lr] = pack2(av.w, av.w);
            Bs[q][lc+0][bofs] = wv.x;
            Bs[q][lc+1][bofs] = wv.y;
            Bs[q][lc+2][bofs] = wv.z;
            Bs[q][lc+3][bofs] = wv.w;
        }
        __syncthreads();
    }

    #pragma unroll
    for (int i = 0; i < 8; i++) {
        int m  = m0 + ty*8 + i;
        int bb_ = m / L;
        int l   = m - bb_ * L;
        #pragma unroll
        for (int j = 0; j < 4; j++) {
            float lo, hi;
            unpack2(acc2[i][j], lo, hi);
            int n0j = n0 + tx*8 + 2*j;
            float v0 = lo + bias[n0j];
            float v1 = hi + bias[n0j + 1];
            if (head_major) {
                int hh0 = n0j >> 6, dk0 = n0j & 63;
                int hh1 = (n0j+1) >> 6, dk1 = (n0j+1) & 63;
                C[((size_t)(bb_*H_ + hh0) * L + l) * DK_ + dk0] = v0;
                C[((size_t)(bb_*H_ + hh1) * L + l) * DK_ + dk1] = v1;
            } else {
                C[(size_t)m * DM_ + n0j]     = v0;
                C[(size_t)m * DM_ + n0j + 1] = v1;
            }
        }
    }
}

// Merged Q/K/V projection: grid (64 + 256 + 256, 4).
__global__ void __launch_bounds__(256, 1)
qkv_gemm_kernel(const float* __restrict__ q_in, const float* __restrict__ k_in,
                const float* __restrict__ v_in,
                const float* __restrict__ Wq, const float* __restrict__ bq,
                const float* __restrict__ Wk, const float* __restrict__ bk,
                const float* __restrict__ Wv, const float* __restrict__ bv,
                float* __restrict__ pq, float* __restrict__ pk, float* __restrict__ pv)
{
    const int bx = blockIdx.x;
    const float *A, *W, *bias; float* C; int L, mblk;
    if (bx < 64)        { A = q_in; W = Wq; bias = bq; C = pq; L = LQ_; mblk = bx; }
    else if (bx < 320)  { A = k_in; W = Wk; bias = bk; C = pk; L = LM_; mblk = bx - 64; }
    else                { A = v_in; W = Wv; bias = bv; C = pv; L = LM_; mblk = bx - 320; }
    gemm_body(A, W, bias, C, L, 1, mblk * 128, blockIdx.y * 128);
}

// Output projection: plain row-major.
__global__ void __launch_bounds__(256, 1)
out_gemm_kernel(const float* __restrict__ A, const float* __restrict__ W,
                const float* __restrict__ bias, float* __restrict__ C)
{
    gemm_body(A, W, bias, C, LQ_, 0, blockIdx.x * 128, blockIdx.y * 128);
}

// ---------------------------------------------------------------------------
// Fused scores + EXACT top-32 + softmax + V gather — round-13 register-score
// structure with the score loop converted to f32x2 over QUERY ROW-PAIRS:
//   qp[rp][d] = (Q[2rp][d], Q[2rp+1][d]) packed once per block in smem;
//   lane owns keys {c0+sub*32+lane}; 32 fma2 replace 64 FFMA per d4.
// Per-lane-half contraction: t=kx*qx; t=fma(ky,qy,t); t=fma(kz,qz,t);
// t=fma(kw,qw,t); acc+=t — same contraction that passed in round 9
// (rel_err 8.774736e-4). Selection visit order (sub ascending) and the
// selection algorithm are verbatim round 13.
// ---------------------------------------------------------------------------
__global__ void __launch_bounds__(256, 3)
attn_topk_kernel(const float* __restrict__ gq, const float* __restrict__ gk,
                 const float* __restrict__ gv, float* __restrict__ gx)
{
    extern __shared__ float sm[];
    ull*   qp = (ull*)(sm + OFF_QP);   // 16 rp x 64 dims, f32x2 packed
    float* ks = sm + OFF_KS;           // xor-swizzled float4 K tile

    const int t    = threadIdx.x;
    const int lane = t & 31;
    const int w    = t >> 5;               // warp id; owns rows 4w..4w+3
    const int qt0  = blockIdx.x * QT;
    const int h    = blockIdx.y;
    const int b    = blockIdx.z;
    const unsigned FULL = 0xffffffffu;

    // ---- pack Q row-pairs into smem (once per block) ----
    const float* qbase = gq + ((size_t)(b*H_ + h) * LQ_ + qt0) * DK_;
    #pragma unroll
    for (int i = t; i < (QT/2)*DK_; i += 256) {
        int rp = i >> 6, d = i & 63;
        float lo = qbase[(size_t)(2*rp)   * DK_ + d];
        float hi = qbase[(size_t)(2*rp+1) * DK_ + d];
        qp[i] = pack2(lo, hi);
    }

    const float* kbase = gk + (size_t)(b*H_ + h) * LM_ * DK_;

    // running top-32 state for the four rows owned by this warp
    unsigned bval[4] = {0u, 0u, 0u, 0u};
    int      bidx[4] = {0, 0, 0, 0};
    unsigned m[4]    = {0u, 0u, 0u, 0u};

    // this lane's 4 key indices within a chunk (sub*32 + lane)
    const int key0 = lane;
    const int key1 = 32 + lane;
    const int key2 = 64 + lane;
    const int key3 = 96 + lane;

    // this warp's two query row-pairs
    const ull* qrp0 = qp + (2*w)     * DK_;   // rows 4w, 4w+1
    const ull* qrp1 = qp + (2*w + 1) * DK_;   // rows 4w+2, 4w+3

    #pragma unroll 1
    for (int c0 = 0; c0 < LM_; c0 += CK) {
        __syncthreads();  // all warps done reading ks of previous chunk
                          // (also covers qp prep on first iteration)

        // ---- stage K chunk (CK x 64) with XOR swizzle: conflict-free ----
        #pragma unroll
        for (int i = t; i < CK*16; i += 256) {
            int row = i >> 4, col = i & 15;
            float4 v4 = ((const float4*)(kbase + (size_t)(c0 + row) * DK_))[col];
            ((float4*)ks)[(row << 4) | (col ^ (row & 15))] = v4;
        }
        __syncthreads();

        // ---- scores in f32x2 registers: 4 keys x 2 row-pairs ----
        ull acc2[4][2];   // [sub][rp]
        #pragma unroll
        for (int sub = 0; sub < 4; sub++) {
            acc2[sub][0] = pack2(0.f, 0.f);
            acc2[sub][1] = pack2(0.f, 0.f);
        }

        {
            const float4* ks4 = (const float4*)ks;
            #pragma unroll 4
            for (int d4 = 0; d4 < DK_/4; d4++) {
                float4 kv0 = ks4[(key0 << 4) | (d4 ^ (key0 & 15))];
                float4 kv1 = ks4[(key1 << 4) | (d4 ^ (key1 & 15))];
                float4 kv2 = ks4[(key2 << 4) | (d4 ^ (key2 & 15))];
                float4 kv3 = ks4[(key3 << 4) | (d4 ^ (key3 & 15))];

                ulonglong2 qa0 = *(const ulonglong2*)(qrp0 + d4*4);
                ulonglong2 qb0 = *(const ulonglong2*)(qrp0 + d4*4 + 2);
                ulonglong2 qa1 = *(const ulonglong2*)(qrp1 + d4*4);
                ulonglong2 qb1 = *(const ulonglong2*)(qrp1 + d4*4 + 2);

                ull kx[4], ky[4], kz[4], kw[4];
                kx[0]=pack2(kv0.x,kv0.x); ky[0]=pack2(kv0.y,kv0.y);
                kz[0]=pack2(kv0.z,kv0.z); kw[0]=pack2(kv0.w,kv0.w);
                kx[1]=pack2(kv1.x,kv1.x); ky[1]=pack2(kv1.y,kv1.y);
                kz[1]=pack2(kv1.z,kv1.z); kw[1]=pack2(kv1.w,kv1.w);
                kx[2]=pack2(kv2.x,kv2.x); ky[2]=pack2(kv2.y,kv2.y);
                kz[2]=pack2(kv2.z,kv2.z); kw[2]=pack2(kv2.w,kv2.w);
                kx[3]=pack2(kv3.x,kv3.x); ky[3]=pack2(kv3.y,kv3.y);
                kz[3]=pack2(kv3.z,kv3.z); kw[3]=pack2(kv3.w,kv3.w);

                #pragma unroll
                for (int sub = 0; sub < 4; sub++) {
                    ull t0 = mul2(kx[sub], qa0.x);
                    t0 = fma2(ky[sub], qa0.y, t0);
                    t0 = fma2(kz[sub], qb0.x, t0);
                    t0 = fma2(kw[sub], qb0.y, t0);
                    acc2[sub][0] = add2(acc2[sub][0], t0);

                    ull t1 = mul2(kx[sub], qa1.x);
                    t1 = fma2(ky[sub], qa1.y, t1);
                    t1 = fma2(kz[sub], qb1.x, t1);
                    t1 = fma2(kw[sub], qb1.y, t1);
                    acc2[sub][1] = add2(acc2[sub][1], t1);
                }
            }
        }

        // unpack to per-row ordered uints: uu[sub][r], r = 2*rp + half
        unsigned uu[4][4];
        #pragma unroll
        for (int sub = 0; sub < 4; sub++) {
            float lo0, hi0, lo1, hi1;
            unpack2(acc2[sub][0], lo0, hi0);
            unpack2(acc2[sub][1], lo1, hi1);
            uu[sub][0] = ordu(lo0 * 0.125f);   // 1/sqrt(64)
            uu[sub][1] = ordu(hi0 * 0.125f);
            uu[sub][2] = ordu(lo1 * 0.125f);
            uu[sub][3] = ordu(hi1 * 0.125f);
        }

        // ---- select on register scores; batch order: sub ascending ----
        #pragma unroll 1
        for (int r = 0; r < 4; r++) {
            unsigned u0 = uu[0][r], u1 = uu[1][r], u2 = uu[2][r], u3 = uu[3][r];

            if (c0 != 0) {
                // fast path: skip row if nothing exceeds m[r] (exact: m is
                // monotone non-decreasing, so skipping is equivalent).
                bool any = (u0 > m[r]) | (u1 > m[r]) | (u2 > m[r]) | (u3 > m[r]);
                if (__ballot_sync(FULL, any) == 0u) continue;
            }

            #pragma unroll 1
            for (int sub = 0; sub < 4; sub++) {
                unsigned u = (sub == 0) ? u0 : (sub == 1) ? u1 : (sub == 2) ? u2 : u3;
                const int i0 = c0 + sub*32;

                if (c0 == 0 && sub == 0) {          // initial fill
                    bval[r] = u; bidx[r] = lane;
                    m[r] = __reduce_min_sync(FULL, bval[r]);
                    continue;
                }

                unsigned hit = __ballot_sync(FULL, u > m[r]);
                while (hit) {                        // warp-uniform rare path
                    int s = __ffs(hit) - 1; hit &= hit - 1;
                    unsigned uc = __shfl_sync(FULL, u, s);
                    if (uc > m[r]) {                 // recheck vs updated m
                        int ic = i0 + s;
                        unsigned em = __ballot_sync(FULL, bval[r] == m[r]);
                        int el;
                        if (__popc(em) > 1) {
                            // tie on min: evict LARGER index (jax keeps lower)
                            int cb = ((em >> lane) & 1) ? bidx[r] : -1;
                            int mx = __reduce_max_sync(FULL, cb);
                            el = __ffs(__ballot_sync(FULL,
                                    (bval[r] == m[r]) && (bidx[r] == mx))) - 1;
                        } else {
                            el = __ffs(em) - 1;
                        }
                        if (lane == el) { bval[r] = uc; bidx[r] = ic; }
                        m[r] = __reduce_min_sync(FULL, bval[r]);
                    }
                }
            }
        }
    }

    // ---- softmax + weighted V gather for the four rows ----
    const float* vbase = gv + (size_t)(b*H_ + h) * LM_ * DK_;
    #pragma unroll 1
    for (int rr = 0; rr < 4; rr++) {
        float v  = iordu(bval[rr]);
        float mx = v;
        #pragma unroll
        for (int off = 16; off; off >>= 1)
            mx = fmaxf(mx, __shfl_xor_sync(FULL, mx, off));
        float e = __expf(v - mx);
        float s = e;
        #pragma unroll
        for (int off = 16; off; off >>= 1)
            s += __shfl_xor_sync(FULL, s, off);
        float wgt = e / s;

        float a0 = 0.f, a1 = 0.f;
        #pragma unroll 4
        for (int it = 0; it < TOPK_; it++) {
            float wi = __shfl_sync(FULL, wgt, it);
            int   ki = __shfl_sync(FULL, bidx[rr], it);
            const float* vr = vbase + (size_t)ki * DK_;
            a0 = fmaf(wi, vr[lane],      a0);
            a1 = fmaf(wi, vr[lane + 32], a1);
        }
        float* orow = gx + ((size_t)b * LQ_ + (qt0 + 4*w + rr)) * DM_ + h*DK_;
        orow[lane]      = a0;
        orow[lane + 32] = a1;
    }
}

// ---------------------------------------------------------------------------
extern "C" void kernel_launch(void* const* d_in, const int* in_sizes, int n_in,
                              void* d_out, int out_size)
{
    const float* query = (const float*)d_in[0];
    const float* key   = (const float*)d_in[1];
    const float* value = (const float*)d_in[2];
    const float* Wq    = (const float*)d_in[3];
    const float* bq    = (const float*)d_in[4];
    const float* Wk    = (const float*)d_in[5];
    const float* bk    = (const float*)d_in[6];
    const float* Wv    = (const float*)d_in[7];
    const float* bv    = (const float*)d_in[8];
    const float* Wo    = (const float*)d_in[9];
    const float* bo    = (const float*)d_in[10];
    float* out = (float*)d_out;

    float *pq, *pk, *pv, *px;
    cudaGetSymbolAddress((void**)&pq, g_q);
    cudaGetSymbolAddress((void**)&pk, g_k);
    cudaGetSymbolAddress((void**)&pv, g_v);
    cudaGetSymbolAddress((void**)&px, g_x);

    cudaFuncSetAttribute(attn_topk_kernel,
                         cudaFuncAttributeMaxDynamicSharedMemorySize, SMEM_BYTES);

    // merged Q/K/V projections into head-major scratch (round-8 geometry)
    qkv_gemm_kernel<<<dim3(576, DM_/128), 256>>>(query, key, value,
                                                 Wq, bq, Wk, bk, Wv, bv,
                                                 pq, pk, pv);

    // fused scores + topk + softmax + gather
    attn_topk_kernel<<<dim3(LQ_/QT, H_, B_), 256, SMEM_BYTES>>>(pq, pk, pv, px);

    // output projection (plain row-major)
    out_gemm_kernel<<<dim3(B_*LQ_/128, DM_/128), 256>>>(px, Wo, bo, out);
}